// round 5
// baseline (speedup 1.0000x reference)
#include <cuda_runtime.h>
#include <cstdint>

#define Bc 2
#define Tc 2048
#define Cc 1024
#define Hc 16
#define Dc 64

__device__ float g_q[Bc * Hc * Tc * Dc];
__device__ float g_k[Bc * Hc * Tc * Dc];
__device__ float g_v[Bc * Hc * Tc * Dc];
__device__ float g_y[Bc * Tc * Cc];

// ============================ helpers ============================
__device__ __forceinline__ uint32_t smem_u32(const void* p) {
    uint32_t a;
    asm("{ .reg .u64 t; cvta.to.shared.u64 t, %1; cvt.u32.u64 %0, t; }" : "=r"(a) : "l"(p));
    return a;
}

__device__ __forceinline__ void ldsm_x4(uint32_t addr, uint32_t& d0, uint32_t& d1,
                                        uint32_t& d2, uint32_t& d3) {
    asm volatile("ldmatrix.sync.aligned.m8n8.x4.shared.b16 {%0,%1,%2,%3}, [%4];"
                 : "=r"(d0), "=r"(d1), "=r"(d2), "=r"(d3) : "r"(addr));
}

__device__ __forceinline__ void mma_tf32(float c[4], const uint32_t a[4],
                                         uint32_t b0, uint32_t b1) {
    asm volatile("mma.sync.aligned.m16n8k8.row.col.f32.tf32.tf32.f32 "
                 "{%0,%1,%2,%3}, {%4,%5,%6,%7}, {%8,%9}, {%0,%1,%2,%3};"
                 : "+f"(c[0]), "+f"(c[1]), "+f"(c[2]), "+f"(c[3])
                 : "r"(a[0]), "r"(a[1]), "r"(a[2]), "r"(a[3]), "r"(b0), "r"(b1));
}

__device__ __forceinline__ void tf32split(float v, uint32_t& hi, uint32_t& lo) {
    asm("cvt.rna.tf32.f32 %0, %1;" : "=r"(hi) : "f"(v));
    float r = v - __uint_as_float(hi);
    asm("cvt.rna.tf32.f32 %0, %1;" : "=r"(lo) : "f"(r));
}

// packed f32x2
typedef unsigned long long u64t;
__device__ __forceinline__ u64t ffma2(u64t a, u64t b, u64t c) {
    u64t d; asm("fma.rn.f32x2 %0, %1, %2, %3;" : "=l"(d) : "l"(a), "l"(b), "l"(c)); return d;
}
__device__ __forceinline__ u64t fmul2(u64t a, u64t b) {
    u64t d; asm("mul.rn.f32x2 %0, %1, %2;" : "=l"(d) : "l"(a), "l"(b)); return d;
}
__device__ __forceinline__ u64t pk2(float x, float y) {
    u64t r; asm("mov.b64 %0, {%1, %2};" : "=l"(r) : "f"(x), "f"(y)); return r;
}
__device__ __forceinline__ void up2(u64t v, float& x, float& y) {
    asm("mov.b64 {%0, %1}, %2;" : "=f"(x), "=f"(y) : "l"(v));
}

// ============================================================================
// tf32x3 NT GEMM via mma.sync: C[m,n] = sum_k A[m,k]*B[n,k] + bias[n]
// CTA 128x128, 8 warps (warp tile 64x32), K chunk 32 floats.
// Smem: K-major [row][32] tiles for A/B, hi and lo tf32 copies (4 x 16KB).
// Fragments via ldmatrix.x4.b16 (one 8x8 b16 matrix == 8x4 tf32 fragment).
// MODE 0: scatter to [B,H,T,D]; MODE 1: row-major [M,N].
// ============================================================================
#define GSMEM_BYTES 65536

template <int MODE>
__global__ void __launch_bounds__(256)
gemm_mma(const float* __restrict__ A, const float* __restrict__ B,
         const float* __restrict__ bias, float* __restrict__ C)
{
    extern __shared__ char sm[];
    const uint32_t sAh = smem_u32(sm);
    const uint32_t sAl = sAh + 16384;
    const uint32_t sBh = sAh + 32768;
    const uint32_t sBl = sAh + 49152;

    const int tid  = threadIdx.x;
    const int lane = tid & 31;
    const int wid  = tid >> 5;
    const int wm   = (wid >> 2) << 6;   // 0 or 64 (rows)
    const int wn   = (wid & 3) << 5;    // 0,32,64,96 (cols)
    const int m0   = blockIdx.y << 7;
    const int n0   = blockIdx.x << 7;

    // ldmatrix lane base offsets (bytes), row stride = 32 floats = 128B
    // A tile (16x8 tf32): row = lane&15, col offset = 4*(lane>>4)
    const uint32_t aOff = (uint32_t)((lane & 15) * 128 + ((lane >> 4) << 4));
    // B tiles (two 8x8): row = (lane&7) + 8*(lane>>4), col offset = 4*((lane>>3)&1)
    const uint32_t bOff = (uint32_t)((((lane & 7) + ((lane >> 4) << 3)) * 128) +
                                     (((lane >> 3) & 1) << 4));

    float c[4][4][4];
#pragma unroll
    for (int i = 0; i < 4; i++)
#pragma unroll
        for (int j = 0; j < 4; j++)
#pragma unroll
            for (int q = 0; q < 4; q++) c[i][j][q] = 0.f;

    float4 ra[4], rb[4];
    // prefetch chunk 0: 128 rows x 32 k-floats each for A and B
#pragma unroll
    for (int it = 0; it < 4; it++) {
        int e = tid + (it << 8);
        int row = e >> 3, c4 = e & 7;
        ra[it] = *(const float4*)&A[(size_t)(m0 + row) * 1024 + (c4 << 2)];
        rb[it] = *(const float4*)&B[(size_t)(n0 + row) * 1024 + (c4 << 2)];
    }

    for (int ch = 0; ch < 32; ch++) {
        // STS with tf32 hi/lo split (layout matches global: [row][k])
#pragma unroll
        for (int it = 0; it < 4; it++) {
            int e = tid + (it << 8);
            int row = e >> 3, c4 = e & 7;
            uint32_t byteoff = (uint32_t)(row * 128 + (c4 << 4));
            uint4 h, l;
            tf32split(ra[it].x, h.x, l.x); tf32split(ra[it].y, h.y, l.y);
            tf32split(ra[it].z, h.z, l.z); tf32split(ra[it].w, h.w, l.w);
            *(uint4*)(sm + (sAh - smem_u32(sm)) + byteoff) = h;   // Ah
            *(uint4*)(sm + 16384 + byteoff) = l;                   // Al
            tf32split(rb[it].x, h.x, l.x); tf32split(rb[it].y, h.y, l.y);
            tf32split(rb[it].z, h.z, l.z); tf32split(rb[it].w, h.w, l.w);
            *(uint4*)(sm + 32768 + byteoff) = h;                   // Bh
            *(uint4*)(sm + 49152 + byteoff) = l;                   // Bl
        }
        __syncthreads();

        if (ch + 1 < 32) {
            int k0 = (ch + 1) << 5;
#pragma unroll
            for (int it = 0; it < 4; it++) {
                int e = tid + (it << 8);
                int row = e >> 3, c4 = e & 7;
                ra[it] = *(const float4*)&A[(size_t)(m0 + row) * 1024 + k0 + (c4 << 2)];
                rb[it] = *(const float4*)&B[(size_t)(n0 + row) * 1024 + k0 + (c4 << 2)];
            }
        }

#pragma unroll
        for (int k8 = 0; k8 < 4; k8++) {
            const uint32_t kb = (uint32_t)(k8 << 5);   // 8 floats = 32 bytes
            uint32_t bh[8], bl[8];
            ldsm_x4(sBh + bOff + (uint32_t)(wn << 7) + kb, bh[0], bh[1], bh[2], bh[3]);
            ldsm_x4(sBh + bOff + (uint32_t)(wn << 7) + 2048u + kb, bh[4], bh[5], bh[6], bh[7]);
            ldsm_x4(sBl + bOff + (uint32_t)(wn << 7) + kb, bl[0], bl[1], bl[2], bl[3]);
            ldsm_x4(sBl + bOff + (uint32_t)(wn << 7) + 2048u + kb, bl[4], bl[5], bl[6], bl[7]);
#pragma unroll
            for (int mt = 0; mt < 4; mt++) {
                uint32_t ah[4], al[4];
                uint32_t ao = aOff + (uint32_t)((wm + (mt << 4)) << 7) + kb;
                ldsm_x4(sAh + ao, ah[0], ah[1], ah[2], ah[3]);
                ldsm_x4(sAl + ao, al[0], al[1], al[2], al[3]);
#pragma unroll
                for (int nt = 0; nt < 4; nt++) {
                    mma_tf32(c[mt][nt], ah, bh[2 * nt], bh[2 * nt + 1]);
                    mma_tf32(c[mt][nt], ah, bl[2 * nt], bl[2 * nt + 1]);
                    mma_tf32(c[mt][nt], al, bh[2 * nt], bh[2 * nt + 1]);
                }
            }
        }
        __syncthreads();
    }

    // epilogue: c0,c1 at (m, n..n+1), c2,c3 at (m+8, n..n+1)
#pragma unroll
    for (int mt = 0; mt < 4; mt++) {
#pragma unroll
        for (int nt = 0; nt < 4; nt++) {
            int m = m0 + wm + (mt << 4) + (lane >> 2);
            int n = n0 + wn + (nt << 3) + ((lane & 3) << 1);
            float b0 = bias[n], b1 = bias[n + 1];
            size_t d0, d1;
            if (MODE == 0) {
                int bb = m >> 11, tt = m & 2047, hh = n >> 6, dd = n & 63;
                d0 = ((size_t)((bb * Hc + hh) * Tc + tt) << 6) + dd;
                int m2 = m + 8;
                int bb2 = m2 >> 11, tt2 = m2 & 2047;
                d1 = ((size_t)((bb2 * Hc + hh) * Tc + tt2) << 6) + dd;
            } else {
                d0 = (size_t)m * Cc + n;
                d1 = (size_t)(m + 8) * Cc + n;
            }
            *(float2*)&C[d0] = make_float2(c[mt][nt][0] + b0, c[mt][nt][1] + b1);
            *(float2*)&C[d1] = make_float2(c[mt][nt][2] + b0, c[mt][nt][3] + b1);
        }
    }
}

// ============================================================================
// Flash attention fp32, causal, 64q x 64kv tiles, f32x2-packed FMA.
// Thread (r=tid/4, g=tid%4): scores for keys c=g+4i (i<16), output dims
// [16g,16g+16) via float4 PV loads. Smem XOR-swizzled at float4 granularity.
// ============================================================================
__device__ __forceinline__ int sw4(int row, int c4) { return row * 16 + (c4 ^ (row & 15)); }

__global__ void __launch_bounds__(256)
flash_attn(const float* __restrict__ Q, const float* __restrict__ K,
           const float* __restrict__ V, float* __restrict__ Y)
{
    __shared__ __align__(16) float Qs[64 * 64];
    __shared__ __align__(16) float Ks[64 * 64];
    __shared__ __align__(16) float Vs[64 * 64];

    const int bh  = blockIdx.y;
    const int b   = bh >> 4;
    const int h   = bh & 15;
    const int m0  = blockIdx.x << 6;
    const int tid = threadIdx.x;
    const int r   = tid >> 2;
    const int g   = tid & 3;
    const size_t base = (size_t)bh * Tc * Dc;

#pragma unroll
    for (int it = 0; it < 4; it++) {
        int e = tid + (it << 8);
        int rr = e >> 4, c4 = e & 15;
        float4 v = *(const float4*)&Q[base + (size_t)(m0 + rr) * Dc + (c4 << 2)];
        v.x *= 0.125f; v.y *= 0.125f; v.z *= 0.125f; v.w *= 0.125f;
        ((float4*)Qs)[sw4(rr, c4)] = v;
    }

    u64t acc[8];
#pragma unroll
    for (int i = 0; i < 8; i++) acc[i] = 0ull;
    float m_i = -1e30f, l_i = 0.f;

    const int nkv = blockIdx.x + 1;
    for (int j = 0; j < nkv; j++) {
        const int n0 = j << 6;
        __syncthreads();
#pragma unroll
        for (int it = 0; it < 4; it++) {
            int e = tid + (it << 8);
            int rr = e >> 4, c4 = e & 15;
            ((float4*)Ks)[sw4(rr, c4)] =
                *(const float4*)&K[base + (size_t)(n0 + rr) * Dc + (c4 << 2)];
            ((float4*)Vs)[sw4(rr, c4)] =
                *(const float4*)&V[base + (size_t)(n0 + rr) * Dc + (c4 << 2)];
        }
        __syncthreads();

        u64t s2[16];
#pragma unroll
        for (int i = 0; i < 16; i++) s2[i] = 0ull;
#pragma unroll
        for (int c4 = 0; c4 < 16; c4++) {
            ulonglong2 q = *(const ulonglong2*)&((float4*)Qs)[sw4(r, c4)];
#pragma unroll
            for (int i = 0; i < 16; i++) {
                ulonglong2 k = *(const ulonglong2*)&((float4*)Ks)[sw4(g + (i << 2), c4)];
                s2[i] = ffma2(q.x, k.x, s2[i]);
                s2[i] = ffma2(q.y, k.y, s2[i]);
            }
        }

        const bool diag = (j == nkv - 1);
        float s[16];
        float mloc = -1e30f;
#pragma unroll
        for (int i = 0; i < 16; i++) {
            float a, bb2; up2(s2[i], a, bb2);
            s[i] = a + bb2;
            if (diag && (n0 + g + (i << 2)) > (m0 + r)) s[i] = -1e30f;
            mloc = fmaxf(mloc, s[i]);
        }
        mloc = fmaxf(mloc, __shfl_xor_sync(0xffffffffu, mloc, 1));
        mloc = fmaxf(mloc, __shfl_xor_sync(0xffffffffu, mloc, 2));
        float m_new = fmaxf(m_i, mloc);
        float alpha = __expf(m_i - m_new);
        float lloc = 0.f;
#pragma unroll
        for (int i = 0; i < 16; i++) {
            s[i] = __expf(s[i] - m_new);
            lloc += s[i];
        }
        lloc += __shfl_xor_sync(0xffffffffu, lloc, 1);
        lloc += __shfl_xor_sync(0xffffffffu, lloc, 2);
        l_i = l_i * alpha + lloc;
        m_i = m_new;
        u64t al2 = pk2(alpha, alpha);
#pragma unroll
        for (int i = 0; i < 8; i++) acc[i] = fmul2(acc[i], al2);

#pragma unroll
        for (int cIdx = 0; cIdx < 64; cIdx++) {
            float p = __shfl_sync(0xffffffffu, s[cIdx >> 2], cIdx & 3, 4);
            u64t p2 = pk2(p, p);
            int xr = cIdx & 15;
#pragma unroll
            for (int jj = 0; jj < 4; jj++) {
                ulonglong2 v = *(const ulonglong2*)&Vs[(cIdx << 6) + ((((g << 2) + jj) ^ xr) << 2)];
                acc[2 * jj]     = ffma2(p2, v.x, acc[2 * jj]);
                acc[2 * jj + 1] = ffma2(p2, v.y, acc[2 * jj + 1]);
            }
        }
    }

    const float inv = 1.0f / l_i;
    const size_t orow = (size_t)(b * Tc + m0 + r) * Cc + (h << 6) + (g << 4);
#pragma unroll
    for (int jj = 0; jj < 4; jj++) {
        float x0, x1, x2, x3;
        up2(acc[2 * jj], x0, x1);
        up2(acc[2 * jj + 1], x2, x3);
        *(float4*)&Y[orow + (jj << 2)] = make_float4(x0 * inv, x1 * inv, x2 * inv, x3 * inv);
    }
}

// ============================================================================
extern "C" void kernel_launch(void* const* d_in, const int* in_sizes, int n_in,
                              void* d_out, int out_size)
{
    const float* x  = (const float*)d_in[0];
    const float* Wk = (const float*)d_in[1];
    const float* bk = (const float*)d_in[2];
    const float* Wq = (const float*)d_in[3];
    const float* bq = (const float*)d_in[4];
    const float* Wv = (const float*)d_in[5];
    const float* bv = (const float*)d_in[6];
    const float* Wp = (const float*)d_in[7];
    const float* bp = (const float*)d_in[8];
    float* out = (float*)d_out;

    float *pq, *pk, *pv, *py;
    cudaGetSymbolAddress((void**)&pq, g_q);
    cudaGetSymbolAddress((void**)&pk, g_k);
    cudaGetSymbolAddress((void**)&pv, g_v);
    cudaGetSymbolAddress((void**)&py, g_y);

    cudaFuncSetAttribute(gemm_mma<0>, cudaFuncAttributeMaxDynamicSharedMemorySize, GSMEM_BYTES);
    cudaFuncSetAttribute(gemm_mma<1>, cudaFuncAttributeMaxDynamicSharedMemorySize, GSMEM_BYTES);

    dim3 gg(Cc / 128, (Bc * Tc) / 128);   // (8, 32)
    gemm_mma<0><<<gg, 256, GSMEM_BYTES>>>(x, Wq, bq, pq);
    gemm_mma<0><<<gg, 256, GSMEM_BYTES>>>(x, Wk, bk, pk);
    gemm_mma<0><<<gg, 256, GSMEM_BYTES>>>(x, Wv, bv, pv);

    dim3 fg(Tc / 64, Bc * Hc);            // (32, 32)
    flash_attn<<<fg, 256>>>(pq, pk, pv, py);

    gemm_mma<1><<<gg, 256, GSMEM_BYTES>>>(py, Wp, bp, out);
}

// round 6
// speedup vs baseline: 2.2028x; 2.2028x over previous
#include <cuda_runtime.h>
#include <cstdint>

#define Bc 2
#define Tc 2048
#define Cc 1024
#define Hc 16
#define Dc 64

__device__ float g_q[Bc * Hc * Tc * Dc];
__device__ float g_k[Bc * Hc * Tc * Dc];
__device__ float g_v[Bc * Hc * Tc * Dc];
__device__ float g_y[Bc * Tc * Cc];

// ---------------- packed f32x2 helpers ----------------
typedef unsigned long long u64t;
__device__ __forceinline__ u64t ffma2(u64t a, u64t b, u64t c) {
    u64t d; asm("fma.rn.f32x2 %0, %1, %2, %3;" : "=l"(d) : "l"(a), "l"(b), "l"(c)); return d;
}
__device__ __forceinline__ u64t fmul2(u64t a, u64t b) {
    u64t d; asm("mul.rn.f32x2 %0, %1, %2;" : "=l"(d) : "l"(a), "l"(b)); return d;
}
__device__ __forceinline__ u64t pk2(float x, float y) {
    u64t r; asm("mov.b64 %0, {%1, %2};" : "=l"(r) : "f"(x), "f"(y)); return r;
}
__device__ __forceinline__ void up2(u64t v, float& x, float& y) {
    asm("mov.b64 {%0, %1}, %2;" : "=f"(x), "=f"(y) : "l"(v));
}

// ============================================================================
// NT GEMM: C[m,n] = sum_k A[m,k]*B[n,k] + bias[n]. fp32, f32x2-packed FMA.
// CTA 128x128, K chunk 16, register prefetch, 8x8 per-thread tile
// (acc packed as 8x4 u64 pairs over n). MODE 0: scatter [B,H,T,D]; 1: [M,N].
// ============================================================================
#define GBM 128
#define GBN 128
#define GBK 16

template <int MODE>
__global__ void __launch_bounds__(256)
gemm_nt(const float* __restrict__ A, const float* __restrict__ B,
        const float* __restrict__ bias, float* __restrict__ C,
        int M, int N, int K)
{
    __shared__ __align__(16) float As[GBK][GBM];
    __shared__ __align__(16) float Bs[GBK][GBN];

    const int tid = threadIdx.x;
    const int m0 = blockIdx.y * GBM;
    const int n0 = blockIdx.x * GBN;
    const int row = (tid >> 4) << 3;
    const int col = (tid & 15) << 3;

    u64t acc2[8][4];
#pragma unroll
    for (int i = 0; i < 8; i++)
#pragma unroll
        for (int j = 0; j < 4; j++) acc2[i][j] = 0ull;

    float4 ra[2], rb[2];
#pragma unroll
    for (int it = 0; it < 2; it++) {
        int e = tid + it * 256;
        int r = e >> 2, c4 = (e & 3) << 2;
        ra[it] = *reinterpret_cast<const float4*>(&A[(size_t)(m0 + r) * K + c4]);
        rb[it] = *reinterpret_cast<const float4*>(&B[(size_t)(n0 + r) * K + c4]);
    }

    for (int k0 = 0; k0 < K; k0 += GBK) {
#pragma unroll
        for (int it = 0; it < 2; it++) {
            int e = tid + it * 256;
            int r = e >> 2, c4 = (e & 3) << 2;
            As[c4 + 0][r] = ra[it].x; As[c4 + 1][r] = ra[it].y;
            As[c4 + 2][r] = ra[it].z; As[c4 + 3][r] = ra[it].w;
            Bs[c4 + 0][r] = rb[it].x; Bs[c4 + 1][r] = rb[it].y;
            Bs[c4 + 2][r] = rb[it].z; Bs[c4 + 3][r] = rb[it].w;
        }
        __syncthreads();

        if (k0 + GBK < K) {
#pragma unroll
            for (int it = 0; it < 2; it++) {
                int e = tid + it * 256;
                int r = e >> 2, c4 = (e & 3) << 2;
                ra[it] = *reinterpret_cast<const float4*>(&A[(size_t)(m0 + r) * K + k0 + GBK + c4]);
                rb[it] = *reinterpret_cast<const float4*>(&B[(size_t)(n0 + r) * K + k0 + GBK + c4]);
            }
        }

#pragma unroll
        for (int k = 0; k < GBK; k++) {
            float a[8];
            *reinterpret_cast<float4*>(&a[0]) = *reinterpret_cast<const float4*>(&As[k][row]);
            *reinterpret_cast<float4*>(&a[4]) = *reinterpret_cast<const float4*>(&As[k][row + 4]);
            ulonglong2 b01 = *reinterpret_cast<const ulonglong2*>(&Bs[k][col]);
            ulonglong2 b23 = *reinterpret_cast<const ulonglong2*>(&Bs[k][col + 4]);
            u64t bb[4] = {b01.x, b01.y, b23.x, b23.y};
#pragma unroll
            for (int i = 0; i < 8; i++) {
                u64t ad = pk2(a[i], a[i]);
#pragma unroll
                for (int j = 0; j < 4; j++) acc2[i][j] = ffma2(ad, bb[j], acc2[i][j]);
            }
        }
        __syncthreads();
    }

#pragma unroll
    for (int i = 0; i < 8; i++) {
        int m = m0 + row + i;
        float v[8];
#pragma unroll
        for (int j = 0; j < 4; j++) up2(acc2[i][j], v[2 * j], v[2 * j + 1]);
#pragma unroll
        for (int j = 0; j < 8; j++) {
            int n = n0 + col + j;
            float val = v[j] + bias[n];
            if (MODE == 0) {
                int bb = m >> 11, tt = m & 2047, hh = n >> 6, dd = n & 63;
                C[((size_t)((bb * Hc + hh) * Tc + tt) << 6) + dd] = val;
            } else {
                C[(size_t)m * N + n] = val;
            }
        }
    }
}

// ============================================================================
// Flash attention fp32, causal, 64q x 64kv tiles, 256 threads.
// Thread (qg=tid>>4, kg=tid&15): scores 4q x 4k block (rows 4qg.., cols 4kg..),
// output 4q x 4d block (dims 4kg..). Scores exchanged via transposed smem P.
// Swizzle: float4 col' = c4 ^ ((row + row>>4) & 15)  -> conflict-free for all
// row-strided access patterns used here.
// ============================================================================
__device__ __forceinline__ int swf(int row, int c4) {
    return (row << 4) + (c4 ^ ((row + (row >> 4)) & 15));
}

#define FSMEM_BYTES (4 * 64 * 64 * 4)   // Qs,Ks,Vs,Ps = 64KB

__global__ void __launch_bounds__(256)
flash_attn(const float* __restrict__ Q, const float* __restrict__ K,
           const float* __restrict__ V, float* __restrict__ Y)
{
    extern __shared__ __align__(16) float fs[];
    float* Qs = fs;
    float* Ks = fs + 4096;
    float* Vs = fs + 8192;
    float* Ps = fs + 12288;

    const int bh  = blockIdx.y;
    const int b   = bh >> 4;
    const int h   = bh & 15;
    const int qtile = gridDim.x - 1 - blockIdx.x;   // longest blocks first
    const int m0  = qtile << 6;
    const int tid = threadIdx.x;
    const int qg  = tid >> 4;      // 0..15
    const int kg  = tid & 15;      // 0..15
    const int q0  = qg << 2;
    const size_t base = (size_t)bh * Tc * Dc;

    // load Q tile (pre-scaled by 1/sqrt(D))
#pragma unroll
    for (int it = 0; it < 4; it++) {
        int e = tid + (it << 8);
        int rr = e >> 4, c4 = e & 15;
        float4 v = *(const float4*)&Q[base + (size_t)(m0 + rr) * Dc + (c4 << 2)];
        v.x *= 0.125f; v.y *= 0.125f; v.z *= 0.125f; v.w *= 0.125f;
        ((float4*)Qs)[swf(rr, c4)] = v;
    }

    u64t acc2[4][2];
#pragma unroll
    for (int i = 0; i < 4; i++) { acc2[i][0] = 0ull; acc2[i][1] = 0ull; }
    float m[4], l[4];
#pragma unroll
    for (int i = 0; i < 4; i++) { m[i] = -1e30f; l[i] = 0.f; }

    const int nkv = qtile + 1;
    for (int j = 0; j < nkv; j++) {
        const int n0 = j << 6;
        __syncthreads();   // protect Ks/Vs/Ps from previous iter readers
#pragma unroll
        for (int it = 0; it < 4; it++) {
            int e = tid + (it << 8);
            int rr = e >> 4, c4 = e & 15;
            ((float4*)Ks)[swf(rr, c4)] =
                *(const float4*)&K[base + (size_t)(n0 + rr) * Dc + (c4 << 2)];
            ((float4*)Vs)[swf(rr, c4)] =
                *(const float4*)&V[base + (size_t)(n0 + rr) * Dc + (c4 << 2)];
        }
        __syncthreads();

        // ---- QK: s[qi][kj] = Q[q0+qi,:] . K[4kg+kj,:] (packed over d) ----
        u64t s2[4][4];
#pragma unroll
        for (int qi = 0; qi < 4; qi++)
#pragma unroll
            for (int kj = 0; kj < 4; kj++) s2[qi][kj] = 0ull;
#pragma unroll
        for (int c4 = 0; c4 < 16; c4++) {
            ulonglong2 q2[4], k2[4];
#pragma unroll
            for (int qi = 0; qi < 4; qi++)
                q2[qi] = ((const ulonglong2*)Qs)[swf(q0 + qi, c4)];
#pragma unroll
            for (int kj = 0; kj < 4; kj++)
                k2[kj] = ((const ulonglong2*)Ks)[swf((kg << 2) + kj, c4)];
#pragma unroll
            for (int qi = 0; qi < 4; qi++)
#pragma unroll
                for (int kj = 0; kj < 4; kj++) {
                    s2[qi][kj] = ffma2(q2[qi].x, k2[kj].x, s2[qi][kj]);
                    s2[qi][kj] = ffma2(q2[qi].y, k2[kj].y, s2[qi][kj]);
                }
        }
        float s[4][4];
#pragma unroll
        for (int qi = 0; qi < 4; qi++)
#pragma unroll
            for (int kj = 0; kj < 4; kj++) {
                float a, bb; up2(s2[qi][kj], a, bb);
                s[qi][kj] = a + bb;
            }

        // causal mask (diagonal tile only)
        if (j == nkv - 1) {
#pragma unroll
            for (int qi = 0; qi < 4; qi++)
#pragma unroll
                for (int kj = 0; kj < 4; kj++)
                    if (((kg << 2) + kj) > (q0 + qi)) s[qi][kj] = -1e30f;
        }

        // ---- online softmax (reduce across the 16 kg lanes) ----
        float mx[4];
#pragma unroll
        for (int qi = 0; qi < 4; qi++)
            mx[qi] = fmaxf(fmaxf(s[qi][0], s[qi][1]), fmaxf(s[qi][2], s[qi][3]));
#pragma unroll
        for (int off = 1; off < 16; off <<= 1)
#pragma unroll
            for (int qi = 0; qi < 4; qi++)
                mx[qi] = fmaxf(mx[qi], __shfl_xor_sync(0xffffffffu, mx[qi], off));

        float alpha[4], sum[4];
#pragma unroll
        for (int qi = 0; qi < 4; qi++) {
            float mn = fmaxf(m[qi], mx[qi]);
            alpha[qi] = __expf(m[qi] - mn);
            m[qi] = mn;
            float t0 = __expf(s[qi][0] - mn);
            float t1 = __expf(s[qi][1] - mn);
            float t2 = __expf(s[qi][2] - mn);
            float t3 = __expf(s[qi][3] - mn);
            s[qi][0] = t0; s[qi][1] = t1; s[qi][2] = t2; s[qi][3] = t3;
            sum[qi] = (t0 + t1) + (t2 + t3);
        }
#pragma unroll
        for (int off = 1; off < 16; off <<= 1)
#pragma unroll
            for (int qi = 0; qi < 4; qi++)
                sum[qi] += __shfl_xor_sync(0xffffffffu, sum[qi], off);
#pragma unroll
        for (int qi = 0; qi < 4; qi++) {
            l[qi] = l[qi] * alpha[qi] + sum[qi];
            u64t a2 = pk2(alpha[qi], alpha[qi]);
            acc2[qi][0] = fmul2(acc2[qi][0], a2);
            acc2[qi][1] = fmul2(acc2[qi][1], a2);
        }

        // ---- store P transposed: Ps[c][q] ----
#pragma unroll
        for (int kj = 0; kj < 4; kj++) {
            float4 pv = make_float4(s[0][kj], s[1][kj], s[2][kj], s[3][kj]);
            ((float4*)Ps)[swf((kg << 2) + kj, qg)] = pv;
        }
        __syncthreads();

        // ---- PV: acc[qi][d] += P[q0+qi][c] * V[c][4kg+d] ----
#pragma unroll 8
        for (int c = 0; c < 64; c++) {
            float4 p4 = ((const float4*)Ps)[swf(c, qg)];
            ulonglong2 v2 = ((const ulonglong2*)Vs)[swf(c, kg)];
            u64t pd;
            pd = pk2(p4.x, p4.x);
            acc2[0][0] = ffma2(pd, v2.x, acc2[0][0]);
            acc2[0][1] = ffma2(pd, v2.y, acc2[0][1]);
            pd = pk2(p4.y, p4.y);
            acc2[1][0] = ffma2(pd, v2.x, acc2[1][0]);
            acc2[1][1] = ffma2(pd, v2.y, acc2[1][1]);
            pd = pk2(p4.z, p4.z);
            acc2[2][0] = ffma2(pd, v2.x, acc2[2][0]);
            acc2[2][1] = ffma2(pd, v2.y, acc2[2][1]);
            pd = pk2(p4.w, p4.w);
            acc2[3][0] = ffma2(pd, v2.x, acc2[3][0]);
            acc2[3][1] = ffma2(pd, v2.y, acc2[3][1]);
        }
    }

    // ---- output ----
#pragma unroll
    for (int qi = 0; qi < 4; qi++) {
        float inv = 1.0f / l[qi];
        float x0, x1, x2, x3;
        up2(acc2[qi][0], x0, x1);
        up2(acc2[qi][1], x2, x3);
        const size_t orow = (size_t)(b * Tc + m0 + q0 + qi) * Cc + (h << 6) + (kg << 2);
        *(float4*)&Y[orow] = make_float4(x0 * inv, x1 * inv, x2 * inv, x3 * inv);
    }
}

// ============================================================================
extern "C" void kernel_launch(void* const* d_in, const int* in_sizes, int n_in,
                              void* d_out, int out_size)
{
    const float* x  = (const float*)d_in[0];
    const float* Wk = (const float*)d_in[1];
    const float* bk = (const float*)d_in[2];
    const float* Wq = (const float*)d_in[3];
    const float* bq = (const float*)d_in[4];
    const float* Wv = (const float*)d_in[5];
    const float* bv = (const float*)d_in[6];
    const float* Wp = (const float*)d_in[7];
    const float* bp = (const float*)d_in[8];
    float* out = (float*)d_out;

    float *pq, *pk, *pv, *py;
    cudaGetSymbolAddress((void**)&pq, g_q);
    cudaGetSymbolAddress((void**)&pk, g_k);
    cudaGetSymbolAddress((void**)&pv, g_v);
    cudaGetSymbolAddress((void**)&py, g_y);

    cudaFuncSetAttribute(flash_attn, cudaFuncAttributeMaxDynamicSharedMemorySize, FSMEM_BYTES);

    const int M = Bc * Tc, N = Cc, K = Cc;

    dim3 gg(N / GBN, M / GBM);   // (8, 32)
    gemm_nt<0><<<gg, 256>>>(x, Wq, bq, pq, M, N, K);
    gemm_nt<0><<<gg, 256>>>(x, Wk, bk, pk, M, N, K);
    gemm_nt<0><<<gg, 256>>>(x, Wv, bv, pv, M, N, K);

    dim3 fg(Tc / 64, Bc * Hc);   // (32, 32)
    flash_attn<<<fg, 256, FSMEM_BYTES>>>(pq, pk, pv, py);

    gemm_nt<1><<<gg, 256>>>(py, Wp, bp, out, M, N, K);
}